// round 3
// baseline (speedup 1.0000x reference)
#include <cuda_runtime.h>

// RankingLoss: loss = sum_{b, c: tc[c] != label[b]}
//              max(1 + pred[b]·sig[:,tc[c]] - pred[b]·sig[:,label[b]], 0)
// pred (B=16384, D=256) f32, label (B,) i32, tc (C=2000,) i32, sig (D, C) f32.
// Output: scalar f32.

#define BM 128
#define BN 128
#define BK 16
#define TM 8
#define TN 8
#define MAX_B 16384
#define MAX_PART 4096

__device__ float g_gt[MAX_B];
__device__ float g_partial[MAX_PART];

// ---------------- gt kernel: one warp per row ----------------
__global__ void gt_kernel(const float* __restrict__ pred,
                          const int* __restrict__ label,
                          const float* __restrict__ sig,
                          int B, int D, int C) {
    int warps_per_block = blockDim.x >> 5;
    int b = blockIdx.x * warps_per_block + (threadIdx.x >> 5);
    if (b >= B) return;
    int lane = threadIdx.x & 31;
    int lb = label[b];
    const float* prow = pred + (long long)b * D;
    float s = 0.f;
    for (int d = lane; d < D; d += 32)
        s += prow[d] * sig[(long long)d * C + lb];
    #pragma unroll
    for (int o = 16; o > 0; o >>= 1)
        s += __shfl_down_sync(0xffffffffu, s, o);
    if (lane == 0) g_gt[b] = s;
}

// ---------------- fused GEMM + hinge kernel ----------------
__global__ __launch_bounds__(256, 2)
void hinge_gemm_kernel(const float* __restrict__ pred,
                       const float* __restrict__ sig,
                       const int* __restrict__ tclass,
                       const int* __restrict__ label,
                       int B, int D, int C) {
    __shared__ float As[BK][BM];   // pred tile, transposed (k-major rows)
    __shared__ float Bs[BK][BN];   // gathered sig tile
    __shared__ int   tcs[BN];      // class ids for this column tile
    __shared__ float red[256];

    const int tid = threadIdx.x;
    const int bRow = blockIdx.y * BM;
    const int bCol = blockIdx.x * BN;
    const int ty = tid >> 4;       // 0..15
    const int tx = tid & 15;       // 0..15

    if (tid < BN) {
        int j = bCol + tid;
        tcs[tid] = (j < C) ? tclass[j] : -1;
    }
    __syncthreads();

    float acc[TM][TN];
    #pragma unroll
    for (int i = 0; i < TM; i++)
        #pragma unroll
        for (int j = 0; j < TN; j++) acc[i][j] = 0.f;

    for (int k0 = 0; k0 < D; k0 += BK) {
        // Load A tile (128 rows x 16 k) as float4, store transposed.
        #pragma unroll
        for (int i = 0; i < 2; i++) {
            int slot = tid + i * 256;          // 0..511 float4 slots
            int r  = slot >> 2;                // row within tile
            int k4 = (slot & 3) << 2;          // k offset: 0,4,8,12
            float4 v = *(const float4*)&pred[(long long)(bRow + r) * D + k0 + k4];
            As[k4 + 0][r] = v.x;
            As[k4 + 1][r] = v.y;
            As[k4 + 2][r] = v.z;
            As[k4 + 3][r] = v.w;
        }
        // Load B tile (16 k x 128 j), gathered through tcs (coalesced-ish along j).
        #pragma unroll
        for (int i = 0; i < 8; i++) {
            int slot = tid + i * 256;          // 0..2047
            int k = slot >> 7;                 // 0..15
            int j = slot & 127;
            int cls = tcs[j];
            Bs[k][j] = (cls >= 0) ? sig[(long long)(k0 + k) * C + cls] : 0.f;
        }
        __syncthreads();

        #pragma unroll
        for (int k = 0; k < BK; k++) {
            float4 a0 = *(const float4*)&As[k][ty * TM];
            float4 a1 = *(const float4*)&As[k][ty * TM + 4];
            float4 b0 = *(const float4*)&Bs[k][tx * TN];
            float4 b1 = *(const float4*)&Bs[k][tx * TN + 4];
            float ar[TM] = {a0.x, a0.y, a0.z, a0.w, a1.x, a1.y, a1.z, a1.w};
            float br[TN] = {b0.x, b0.y, b0.z, b0.w, b1.x, b1.y, b1.z, b1.w};
            #pragma unroll
            for (int i = 0; i < TM; i++)
                #pragma unroll
                for (int j = 0; j < TN; j++)
                    acc[i][j] = fmaf(ar[i], br[j], acc[i][j]);
        }
        __syncthreads();
    }

    // Epilogue: hinge + mask, accumulate per-thread then block-reduce.
    float lsum = 0.f;
    #pragma unroll
    for (int i = 0; i < TM; i++) {
        int r = bRow + ty * TM + i;
        float base = 1.0f - g_gt[r];
        int lb = label[r];
        #pragma unroll
        for (int j = 0; j < TN; j++) {
            int cls = tcs[tx * TN + j];
            if (cls >= 0 && cls != lb) {
                float h = acc[i][j] + base;
                lsum += fmaxf(h, 0.f);
            }
        }
    }
    red[tid] = lsum;
    __syncthreads();
    #pragma unroll
    for (int s = 128; s > 0; s >>= 1) {
        if (tid < s) red[tid] += red[tid + s];
        __syncthreads();
    }
    if (tid == 0)
        g_partial[blockIdx.y * gridDim.x + blockIdx.x] = red[0];
}

// ---------------- deterministic final reduce ----------------
__global__ void final_reduce_kernel(float* __restrict__ out, int n) {
    __shared__ float red[256];
    int tid = threadIdx.x;
    float s = 0.f;
    for (int i = tid; i < n; i += 256) s += g_partial[i];
    red[tid] = s;
    __syncthreads();
    #pragma unroll
    for (int o = 128; o > 0; o >>= 1) {
        if (tid < o) red[tid] += red[tid + o];
        __syncthreads();
    }
    if (tid == 0) out[0] = red[0];
}

extern "C" void kernel_launch(void* const* d_in, const int* in_sizes, int n_in,
                              void* d_out, int out_size) {
    const float* pred   = (const float*)d_in[0];
    const int*   label  = (const int*)d_in[1];
    const int*   tclass = (const int*)d_in[2];
    const float* sig    = (const float*)d_in[3];
    float* out = (float*)d_out;

    const int B = in_sizes[1];
    const int C = in_sizes[2];
    const int D = in_sizes[0] / B;

    // gt: one warp per row, 8 warps per block
    {
        int warps_per_block = 8;
        int blocks = (B + warps_per_block - 1) / warps_per_block;
        gt_kernel<<<blocks, warps_per_block * 32>>>(pred, label, sig, B, D, C);
    }

    // fused GEMM + hinge
    dim3 grid((C + BN - 1) / BN, (B + BM - 1) / BM);
    hinge_gemm_kernel<<<grid, 256>>>(pred, sig, tclass, label, B, D, C);

    // deterministic final reduction
    int nparts = grid.x * grid.y;
    final_reduce_kernel<<<1, 256>>>(out, nparts);
}

// round 6
// speedup vs baseline: 3.6858x; 3.6858x over previous
#include <cuda_runtime.h>
#include <cuda_bf16.h>
#include <cstdint>

// ============================================================
// RankingLoss via warp-level bf16 mma.sync (sm_80+ PTX, runs on
// tensor pipe without arch-specific 'a' features).
// loss = sum_{b,c: tc[c]!=label[b]} max(1 + pred_b·sigc_c - gt_b, 0)
// pred (16384,256) f32, label (16384,) i32, tc (2000,) i32, sig (256,2000) f32
// ============================================================

#define MAX_B   16384
#define DDIM    256
#define CPAD    2048
#define MAX_PART 4096

__device__ float g_gt[MAX_B];
__device__ float g_partial[MAX_PART];
__device__ __nv_bfloat16 g_predb[MAX_B * DDIM];   // pred bf16, [b][d]
__device__ __nv_bfloat16 g_sgath[CPAD * DDIM];    // gathered sig bf16, [c][d]
__device__ int g_tcs[CPAD];                        // class ids (-1 pad)

// ---------------- prep: pred -> bf16 ----------------
__global__ void prep_pred_kernel(const float* __restrict__ pred, int n8) {
    int i = blockIdx.x * blockDim.x + threadIdx.x;
    if (i >= n8) return;
    const float4* s = (const float4*)pred + i * 2;
    float4 a = s[0], b = s[1];
    __nv_bfloat162 o[4];
    o[0] = __nv_bfloat162(__float2bfloat16(a.x), __float2bfloat16(a.y));
    o[1] = __nv_bfloat162(__float2bfloat16(a.z), __float2bfloat16(a.w));
    o[2] = __nv_bfloat162(__float2bfloat16(b.x), __float2bfloat16(b.y));
    o[3] = __nv_bfloat162(__float2bfloat16(b.z), __float2bfloat16(b.w));
    *(uint4*)&g_predb[(size_t)i * 8] = *(uint4*)o;
}

// ---------------- prep: gather sig columns -> bf16 [c][d] ----------------
__global__ void prep_sig_kernel(const float* __restrict__ sig,
                                const int* __restrict__ tclass, int C) {
    int t = blockIdx.x * blockDim.x + threadIdx.x;   // CPAD*32 threads
    int c = t >> 5;
    int d0 = (t & 31) << 3;
    if (c >= CPAD) return;
    __nv_bfloat162 o[4];
    if (c < C) {
        int cls = tclass[c];
        float v[8];
        #pragma unroll
        for (int i = 0; i < 8; i++) v[i] = sig[(size_t)(d0 + i) * C + cls];
        #pragma unroll
        for (int i = 0; i < 4; i++)
            o[i] = __nv_bfloat162(__float2bfloat16(v[2*i]), __float2bfloat16(v[2*i+1]));
        if ((t & 31) == 0) g_tcs[c] = cls;
    } else {
        #pragma unroll
        for (int i = 0; i < 4; i++) o[i] = __nv_bfloat162(__float2bfloat16(0.f), __float2bfloat16(0.f));
        if ((t & 31) == 0) g_tcs[c] = -1;
    }
    *(uint4*)&g_sgath[(size_t)c * DDIM + d0] = *(uint4*)o;
}

// ---------------- gt: exact fp32, one warp per row ----------------
__global__ void gt_kernel(const float* __restrict__ pred,
                          const int* __restrict__ label,
                          const float* __restrict__ sig,
                          int B, int D, int C) {
    int b = blockIdx.x * (blockDim.x >> 5) + (threadIdx.x >> 5);
    if (b >= B) return;
    int lane = threadIdx.x & 31;
    int lb = label[b];
    const float* prow = pred + (size_t)b * D;
    float s = 0.f;
    for (int d = lane; d < D; d += 32)
        s += prow[d] * sig[(size_t)d * C + lb];
    #pragma unroll
    for (int o = 16; o > 0; o >>= 1) s += __shfl_down_sync(0xffffffffu, s, o);
    if (lane == 0) g_gt[b] = s;
}

// ---------------- fused MMA GEMM + hinge ----------------
// SMEM layout (dynamic): A 64KB, B 64KB, tcs 512B, gt 512B, label 512B, red 1KB
#define A_OFF    0
#define B_OFF    65536
#define TCS_OFF  131072
#define GT_OFF   131584
#define LB_OFF   132096
#define RED_OFF  132608
#define SMEM_TOTAL 133632

__device__ __forceinline__ uint32_t smem_u32(const void* p) {
    uint32_t a;
    asm("{ .reg .u64 t; cvta.to.shared.u64 t, %1; cvt.u32.u64 %0, t; }" : "=r"(a) : "l"(p));
    return a;
}

// Load 128x256 bf16 tile into SMEM, 512B rows, 16B-unit swizzle u ^= (row&7).
__device__ __forceinline__ void load_tile(char* dst, const __nv_bfloat16* src,
                                          int row0, int tid) {
    #pragma unroll
    for (int it = 0; it < 16; it++) {
        int unit = tid + it * 256;           // 0..4095
        int r = unit >> 5;
        int u = unit & 31;
        uint4 v = *(const uint4*)&src[(size_t)(row0 + r) * DDIM + u * 8];
        *(uint4*)(dst + r * 512 + ((u ^ (r & 7)) << 4)) = v;
    }
}

#define LDMX4(r0, r1, r2, r3, a) \
    asm volatile("ldmatrix.sync.aligned.m8n8.x4.shared.b16 {%0,%1,%2,%3}, [%4];" \
        : "=r"(r0), "=r"(r1), "=r"(r2), "=r"(r3) : "r"(a))

#define MMA16816(c, A, b0, b1) \
    asm volatile("mma.sync.aligned.m16n8k16.row.col.f32.bf16.bf16.f32 " \
        "{%0,%1,%2,%3}, {%4,%5,%6,%7}, {%8,%9}, {%0,%1,%2,%3};" \
        : "+f"((c)[0]), "+f"((c)[1]), "+f"((c)[2]), "+f"((c)[3]) \
        : "r"((A)[0]), "r"((A)[1]), "r"((A)[2]), "r"((A)[3]), "r"(b0), "r"(b1))

__global__ __launch_bounds__(256, 1)
void hinge_mma_kernel(const int* __restrict__ label) {
    extern __shared__ char smem[];
    const uint32_t sb = smem_u32(smem);
    const int tid = threadIdx.x, lane = tid & 31, wid = tid >> 5;
    const int c0 = blockIdx.x * 128;       // class-tile base
    const int r0 = blockIdx.y * 128;       // row-tile base

    // Stage tiles + metadata
    load_tile(smem + A_OFF, g_predb, r0, tid);
    load_tile(smem + B_OFF, g_sgath, c0, tid);
    if (tid < 128) {
        ((int*)(smem + TCS_OFF))[tid]  = g_tcs[c0 + tid];
        ((float*)(smem + GT_OFF))[tid] = g_gt[r0 + tid];
        ((int*)(smem + LB_OFF))[tid]   = label[r0 + tid];
    }
    __syncthreads();

    // Warp layout: 4 (m) x 2 (n); warp tile 32 x 64
    const int wm = (wid & 3) * 32;
    const int wn = (wid >> 2) * 64;

    float acc[2][8][4];
    #pragma unroll
    for (int mi = 0; mi < 2; mi++)
        #pragma unroll
        for (int ni = 0; ni < 8; ni++)
            #pragma unroll
            for (int q = 0; q < 4; q++) acc[mi][ni][q] = 0.f;

    // Per-thread fragment base addresses (row part). Swizzle XOR = lane&7 for all.
    const int lrow = lane & 15;
    const uint32_t u0 = (uint32_t)(lane >> 4);
    const uint32_t xr = (uint32_t)(lane & 7);
    uint32_t baseA[2], baseB[4];
    #pragma unroll
    for (int mi = 0; mi < 2; mi++)
        baseA[mi] = sb + A_OFF + (uint32_t)(wm + mi * 16 + lrow) * 512u;
    #pragma unroll
    for (int p = 0; p < 4; p++)
        baseB[p] = sb + B_OFF + (uint32_t)(wn + p * 16 + lrow) * 512u;

    #pragma unroll
    for (int ks = 0; ks < 16; ks++) {
        const uint32_t t = (((uint32_t)(2 * ks) + u0) ^ xr) << 4;
        uint32_t a[2][4];
        LDMX4(a[0][0], a[0][1], a[0][2], a[0][3], baseA[0] + t);
        LDMX4(a[1][0], a[1][1], a[1][2], a[1][3], baseA[1] + t);
        uint32_t b[8][2];
        #pragma unroll
        for (int p = 0; p < 4; p++) {
            uint32_t q0, q1, q2, q3;
            LDMX4(q0, q1, q2, q3, baseB[p] + t);
            b[2*p][0] = q0; b[2*p][1] = q2;     // n-tile 2p
            b[2*p+1][0] = q1; b[2*p+1][1] = q3; // n-tile 2p+1
        }
        #pragma unroll
        for (int mi = 0; mi < 2; mi++)
            #pragma unroll
            for (int ni = 0; ni < 8; ni++)
                MMA16816(acc[mi][ni], a[mi], b[ni][0], b[ni][1]);
    }

    // ---- fused hinge epilogue (accumulators in registers) ----
    const int* tcs = (const int*)(smem + TCS_OFF);
    const float* gts = (const float*)(smem + GT_OFF);
    const int* lbs = (const int*)(smem + LB_OFF);
    float lsum = 0.f;
    #pragma unroll
    for (int mi = 0; mi < 2; mi++) {
        #pragma unroll
        for (int half = 0; half < 2; half++) {
            const int r = wm + mi * 16 + (lane >> 2) + half * 8;  // local row
            const float base = 1.0f - gts[r];
            const int lb = lbs[r];
            #pragma unroll
            for (int ni = 0; ni < 8; ni++) {
                const int cbase = wn + ni * 8 + (lane & 3) * 2;
                #pragma unroll
                for (int e = 0; e < 2; e++) {
                    const int cls = tcs[cbase + e];
                    if (cls >= 0 && cls != lb)
                        lsum += fmaxf(acc[mi][ni][half * 2 + e] + base, 0.f);
                }
            }
        }
    }

    // deterministic block reduce
    float* red = (float*)(smem + RED_OFF);
    red[tid] = lsum;
    __syncthreads();
    #pragma unroll
    for (int s = 128; s > 0; s >>= 1) {
        if (tid < s) red[tid] += red[tid + s];
        __syncthreads();
    }
    if (tid == 0) g_partial[blockIdx.y * gridDim.x + blockIdx.x] = red[0];
}

// ---------------- deterministic final reduce ----------------
__global__ void final_reduce_kernel(float* __restrict__ out, int n) {
    __shared__ float red[256];
    int tid = threadIdx.x;
    float s = 0.f;
    for (int i = tid; i < n; i += 256) s += g_partial[i];
    red[tid] = s;
    __syncthreads();
    #pragma unroll
    for (int o = 128; o > 0; o >>= 1) {
        if (tid < o) red[tid] += red[tid + o];
        __syncthreads();
    }
    if (tid == 0) out[0] = red[0];
}

extern "C" void kernel_launch(void* const* d_in, const int* in_sizes, int n_in,
                              void* d_out, int out_size) {
    const float* pred   = (const float*)d_in[0];
    const int*   label  = (const int*)d_in[1];
    const int*   tclass = (const int*)d_in[2];
    const float* sig    = (const float*)d_in[3];
    float* out = (float*)d_out;

    const int B = in_sizes[1];
    const int C = in_sizes[2];
    const int D = in_sizes[0] / B;

    // prep
    {
        int n8 = B * D / 8;
        prep_pred_kernel<<<(n8 + 255) / 256, 256>>>(pred, n8);
    }
    prep_sig_kernel<<<(CPAD * 32) / 256, 256>>>(sig, tclass, C);

    // gt (exact fp32)
    gt_kernel<<<(B + 7) / 8, 256>>>(pred, label, sig, B, D, C);

    // fused MMA GEMM + hinge
    cudaFuncSetAttribute(hinge_mma_kernel, cudaFuncAttributeMaxDynamicSharedMemorySize, SMEM_TOTAL);
    dim3 grid(CPAD / 128, B / 128);
    hinge_mma_kernel<<<grid, 256, SMEM_TOTAL>>>(label);

    // final reduce
    final_reduce_kernel<<<1, 256>>>(out, grid.x * grid.y);
}

// round 7
// speedup vs baseline: 4.6118x; 1.2512x over previous
#include <cuda_runtime.h>
#include <cuda_bf16.h>
#include <cstdint>

// ============================================================
// RankingLoss via warp-level bf16 mma.sync, 16-warp CTAs,
// cp.async k-pipelined tile fill, fused hinge epilogue.
// loss = sum_{b,c: tc[c]!=label[b]} max(1 + pred_b·sigc_c - gt_b, 0)
// pred (16384,256) f32, label i32, tc (2000,) i32, sig (256,2000) f32
// ============================================================

#define MAX_B   16384
#define DDIM    256
#define CPAD    2048
#define MAX_PART 4096

__device__ float g_gt[MAX_B];
__device__ float g_partial[MAX_PART];
__device__ __nv_bfloat16 g_predb[MAX_B * DDIM];   // pred bf16 [b][d]
__device__ __nv_bfloat16 g_sgath[CPAD * DDIM];    // gathered sig bf16 [c][d]
__device__ float g_sigT[CPAD * DDIM];             // sig transposed fp32 [c][d]
__device__ int g_tcs[CPAD];                        // class ids (-1 pad)

// ---------------- prep: pred -> bf16 ----------------
__global__ void prep_pred_kernel(const float* __restrict__ pred, int n8) {
    int i = blockIdx.x * blockDim.x + threadIdx.x;
    if (i >= n8) return;
    const float4* s = (const float4*)pred + i * 2;
    float4 a = s[0], b = s[1];
    __nv_bfloat162 o[4];
    o[0] = __nv_bfloat162(__float2bfloat16(a.x), __float2bfloat16(a.y));
    o[1] = __nv_bfloat162(__float2bfloat16(a.z), __float2bfloat16(a.w));
    o[2] = __nv_bfloat162(__float2bfloat16(b.x), __float2bfloat16(b.y));
    o[3] = __nv_bfloat162(__float2bfloat16(b.z), __float2bfloat16(b.w));
    *(uint4*)&g_predb[(size_t)i * 8] = *(uint4*)o;
}

// ---------------- prep: gather sig columns -> bf16 [c][d] ----------------
__global__ void prep_sig_kernel(const float* __restrict__ sig,
                                const int* __restrict__ tclass, int C) {
    int t = blockIdx.x * blockDim.x + threadIdx.x;   // CPAD*32 threads
    int c = t >> 5;
    int d0 = (t & 31) << 3;
    if (c >= CPAD) return;
    __nv_bfloat162 o[4];
    if (c < C) {
        int cls = tclass[c];
        float v[8];
        #pragma unroll
        for (int i = 0; i < 8; i++) v[i] = sig[(size_t)(d0 + i) * C + cls];
        #pragma unroll
        for (int i = 0; i < 4; i++)
            o[i] = __nv_bfloat162(__float2bfloat16(v[2*i]), __float2bfloat16(v[2*i+1]));
        if ((t & 31) == 0) g_tcs[c] = cls;
    } else {
        #pragma unroll
        for (int i = 0; i < 4; i++) o[i] = __nv_bfloat162(__float2bfloat16(0.f), __float2bfloat16(0.f));
        if ((t & 31) == 0) g_tcs[c] = -1;
    }
    *(uint4*)&g_sgath[(size_t)c * DDIM + d0] = *(uint4*)o;
}

// ---------------- transpose sig fp32: [d][c] -> [c][d] ----------------
__global__ void transpose_sig_kernel(const float* __restrict__ sig, int C) {
    __shared__ float t[32][33];
    int cb = blockIdx.x * 32, db = blockIdx.y * 32;
    int tx = threadIdx.x & 31, ty = threadIdx.x >> 5;  // 256 thr: ty 0..7
    #pragma unroll
    for (int i = 0; i < 32; i += 8) {
        int d = db + ty + i, c = cb + tx;
        t[ty + i][tx] = (c < C) ? sig[(size_t)d * C + c] : 0.f;
    }
    __syncthreads();
    #pragma unroll
    for (int i = 0; i < 32; i += 8) {
        int c = cb + ty + i, d = db + tx;
        if (c < CPAD) g_sigT[(size_t)c * DDIM + d] = t[tx][ty + i];
    }
}

// ---------------- gt: exact fp32, coalesced via sigT ----------------
__global__ void gt_kernel(const float* __restrict__ pred,
                          const int* __restrict__ label, int B) {
    int b = blockIdx.x * (blockDim.x >> 5) + (threadIdx.x >> 5);
    if (b >= B) return;
    int lane = threadIdx.x & 31;
    int lb = label[b];
    const float4* p4 = (const float4*)pred + (size_t)b * 64;
    const float4* s4 = (const float4*)g_sigT + (size_t)lb * 64;
    float4 a0 = p4[lane], a1 = p4[lane + 32];
    float4 c0 = s4[lane], c1 = s4[lane + 32];
    float s = a0.x*c0.x + a0.y*c0.y + a0.z*c0.z + a0.w*c0.w
            + a1.x*c1.x + a1.y*c1.y + a1.z*c1.z + a1.w*c1.w;
    #pragma unroll
    for (int o = 16; o > 0; o >>= 1) s += __shfl_down_sync(0xffffffffu, s, o);
    if (lane == 0) g_gt[b] = s;
}

// ---------------- fused MMA GEMM + hinge ----------------
// CTA tile 128 rows x 256 classes, 512 threads (16 warps, 4m x 4n, warp 32x64).
#define A_OFF    0
#define B_OFF    65536
#define TCS_OFF  196608
#define GT_OFF   197632
#define LB_OFF   198144
#define RED_OFF  198656
#define SMEM_TOTAL 200704

__device__ __forceinline__ uint32_t smem_u32(const void* p) {
    uint32_t a;
    asm("{ .reg .u64 t; cvta.to.shared.u64 t, %1; cvt.u32.u64 %0, t; }" : "=r"(a) : "l"(p));
    return a;
}

#define CP_ASYNC16(dst, src) \
    asm volatile("cp.async.cg.shared.global [%0], [%1], 16;" :: "r"(dst), "l"(src) : "memory")
#define CP_COMMIT() asm volatile("cp.async.commit_group;" ::: "memory")
#define CP_WAIT(n)  asm volatile("cp.async.wait_group %0;" :: "n"(n) : "memory")

#define LDMX4(r0, r1, r2, r3, a) \
    asm volatile("ldmatrix.sync.aligned.m8n8.x4.shared.b16 {%0,%1,%2,%3}, [%4];" \
        : "=r"(r0), "=r"(r1), "=r"(r2), "=r"(r3) : "r"(a))

#define MMA16816(c, A, b0, b1) \
    asm volatile("mma.sync.aligned.m16n8k16.row.col.f32.bf16.bf16.f32 " \
        "{%0,%1,%2,%3}, {%4,%5,%6,%7}, {%8,%9}, {%0,%1,%2,%3};" \
        : "+f"((c)[0]), "+f"((c)[1]), "+f"((c)[2]), "+f"((c)[3]) \
        : "r"((A)[0]), "r"((A)[1]), "r"((A)[2]), "r"((A)[3]), "r"(b0), "r"(b1))

__device__ __forceinline__ void do_kstep(int ks, float (&acc)[2][8][4],
                                         const uint32_t (&baseA)[2],
                                         const uint32_t (&baseB)[4],
                                         uint32_t u0, uint32_t xr) {
    const uint32_t t = (((uint32_t)(2 * ks) + u0) ^ xr) << 4;
    uint32_t a[2][4];
    LDMX4(a[0][0], a[0][1], a[0][2], a[0][3], baseA[0] + t);
    LDMX4(a[1][0], a[1][1], a[1][2], a[1][3], baseA[1] + t);
    uint32_t b[8][2];
    #pragma unroll
    for (int p = 0; p < 4; p++) {
        uint32_t q0, q1, q2, q3;
        LDMX4(q0, q1, q2, q3, baseB[p] + t);
        b[2*p][0] = q0;   b[2*p][1] = q2;
        b[2*p+1][0] = q1; b[2*p+1][1] = q3;
    }
    #pragma unroll
    for (int mi = 0; mi < 2; mi++)
        #pragma unroll
        for (int ni = 0; ni < 8; ni++)
            MMA16816(acc[mi][ni], a[mi], b[ni][0], b[ni][1]);
}

__global__ __launch_bounds__(512, 1)
void hinge_mma_kernel(const int* __restrict__ label) {
    extern __shared__ char smem[];
    const uint32_t sb = smem_u32(smem);
    const int tid = threadIdx.x, lane = tid & 31, wid = tid >> 5;
    const int c0 = blockIdx.x * 256;       // class-tile base
    const int r0 = blockIdx.y * 128;       // row-tile base

    // ---- issue cp.async fills, one commit group per k-chunk (64 k-elems) ----
    #pragma unroll
    for (int ch = 0; ch < 4; ch++) {
        #pragma unroll
        for (int i = 0; i < 2; i++) {          // A: 128 rows x 8 units
            int q = tid + i * 512;
            int row = q >> 3, u = ch * 8 + (q & 7);
            uint32_t dst = sb + A_OFF + (uint32_t)row * 512u + (uint32_t)((u ^ (row & 7)) << 4);
            size_t src = __cvta_generic_to_global(&g_predb[(size_t)(r0 + row) * DDIM + u * 8]);
            CP_ASYNC16(dst, src);
        }
        #pragma unroll
        for (int i = 0; i < 4; i++) {          // B: 256 rows x 8 units
            int q = tid + i * 512;
            int row = q >> 3, u = ch * 8 + (q & 7);
            uint32_t dst = sb + B_OFF + (uint32_t)row * 512u + (uint32_t)((u ^ (row & 7)) << 4);
            size_t src = __cvta_generic_to_global(&g_sgath[(size_t)(c0 + row) * DDIM + u * 8]);
            CP_ASYNC16(dst, src);
        }
        CP_COMMIT();
    }

    // metadata while fills fly
    if (tid < 256) ((int*)(smem + TCS_OFF))[tid] = g_tcs[c0 + tid];
    if (tid < 128) {
        ((float*)(smem + GT_OFF))[tid] = g_gt[r0 + tid];
        ((int*)(smem + LB_OFF))[tid]   = label[r0 + tid];
    }

    // Warp layout: 4 (m) x 4 (n); warp tile 32 x 64
    const int wm = (wid & 3) * 32;
    const int wn = (wid >> 2) * 64;

    float acc[2][8][4];
    #pragma unroll
    for (int mi = 0; mi < 2; mi++)
        #pragma unroll
        for (int ni = 0; ni < 8; ni++)
            #pragma unroll
            for (int q = 0; q < 4; q++) acc[mi][ni][q] = 0.f;

    const int lrow = lane & 15;
    const uint32_t u0 = (uint32_t)(lane >> 4);
    const uint32_t xr = (uint32_t)(lane & 7);
    uint32_t baseA[2], baseB[4];
    #pragma unroll
    for (int mi = 0; mi < 2; mi++)
        baseA[mi] = sb + A_OFF + (uint32_t)(wm + mi * 16 + lrow) * 512u;
    #pragma unroll
    for (int p = 0; p < 4; p++)
        baseB[p] = sb + B_OFF + (uint32_t)(wn + p * 16 + lrow) * 512u;

    // ---- pipelined k phases: wait chunk, barrier, 4 k-steps ----
    CP_WAIT(3); __syncthreads();
    #pragma unroll
    for (int ks = 0; ks < 4; ks++) do_kstep(ks, acc, baseA, baseB, u0, xr);
    CP_WAIT(2); __syncthreads();
    #pragma unroll
    for (int ks = 4; ks < 8; ks++) do_kstep(ks, acc, baseA, baseB, u0, xr);
    CP_WAIT(1); __syncthreads();
    #pragma unroll
    for (int ks = 8; ks < 12; ks++) do_kstep(ks, acc, baseA, baseB, u0, xr);
    CP_WAIT(0); __syncthreads();
    #pragma unroll
    for (int ks = 12; ks < 16; ks++) do_kstep(ks, acc, baseA, baseB, u0, xr);

    // ---- fused hinge epilogue ----
    const int* tcs = (const int*)(smem + TCS_OFF);
    const float* gts = (const float*)(smem + GT_OFF);
    const int* lbs = (const int*)(smem + LB_OFF);
    float lsum = 0.f;
    #pragma unroll
    for (int mi = 0; mi < 2; mi++) {
        #pragma unroll
        for (int half = 0; half < 2; half++) {
            const int r = wm + mi * 16 + (lane >> 2) + half * 8;
            const float base = 1.0f - gts[r];
            const int lb = lbs[r];
            #pragma unroll
            for (int ni = 0; ni < 8; ni++) {
                const int cbase = wn + ni * 8 + (lane & 3) * 2;
                #pragma unroll
                for (int e = 0; e < 2; e++) {
                    const int cls = tcs[cbase + e];
                    if (cls >= 0 && cls != lb)
                        lsum += fmaxf(acc[mi][ni][half * 2 + e] + base, 0.f);
                }
            }
        }
    }

    float* red = (float*)(smem + RED_OFF);
    red[tid] = lsum;
    __syncthreads();
    #pragma unroll
    for (int s = 256; s > 0; s >>= 1) {
        if (tid < s) red[tid] += red[tid + s];
        __syncthreads();
    }
    if (tid == 0) g_partial[blockIdx.y * gridDim.x + blockIdx.x] = red[0];
}

// ---------------- deterministic final reduce ----------------
__global__ void final_reduce_kernel(float* __restrict__ out, int n) {
    __shared__ float red[256];
    int tid = threadIdx.x;
    float s = 0.f;
    for (int i = tid; i < n; i += 256) s += g_partial[i];
    red[tid] = s;
    __syncthreads();
    #pragma unroll
    for (int o = 128; o > 0; o >>= 1) {
        if (tid < o) red[tid] += red[tid + o];
        __syncthreads();
    }
    if (tid == 0) out[0] = red[0];
}

extern "C" void kernel_launch(void* const* d_in, const int* in_sizes, int n_in,
                              void* d_out, int out_size) {
    const float* pred   = (const float*)d_in[0];
    const int*   label  = (const int*)d_in[1];
    const int*   tclass = (const int*)d_in[2];
    const float* sig    = (const float*)d_in[3];
    float* out = (float*)d_out;

    const int B = in_sizes[1];
    const int C = in_sizes[2];
    const int D = in_sizes[0] / B;
    (void)D;

    // prep
    {
        int n8 = B * DDIM / 8;
        prep_pred_kernel<<<(n8 + 255) / 256, 256>>>(pred, n8);
    }
    prep_sig_kernel<<<(CPAD * 32) / 256, 256>>>(sig, tclass, C);
    {
        dim3 tg((C + 31) / 32, DDIM / 32);
        transpose_sig_kernel<<<tg, 256>>>(sig, C);
    }

    // gt (exact fp32, coalesced)
    gt_kernel<<<(B + 7) / 8, 256>>>(pred, label, B);

    // fused MMA GEMM + hinge
    cudaFuncSetAttribute(hinge_mma_kernel, cudaFuncAttributeMaxDynamicSharedMemorySize, SMEM_TOTAL);
    dim3 grid(CPAD / 256, B / 128);
    hinge_mma_kernel<<<grid, 512, SMEM_TOTAL>>>(label);

    // final reduce
    final_reduce_kernel<<<1, 256>>>(out, grid.x * grid.y);
}